// round 9
// baseline (speedup 1.0000x reference)
#include <cuda_runtime.h>
#include <cuda_fp16.h>
#include <cstdint>

#define N_VOX 200000
#define C_CH  128
#define BM    64
#define NTILE (N_VOX / BM)               // 3125 exact
#define EPSV  1e-5f

#define NCHUNK 6                         // 384 / 64
#define MAT_A  8192                      // 64 rows * 128B
#define MAT_W  16384                     // 128 rows * 128B
#define BUFB   (MAT_A + MAT_W)           // 24576
#define SSUM_OFF (3 * BUFB)              // 73728
#define SM_TOTAL (SSUM_OFF + 1024)       // 74752 -> 3 CTAs/SM

// ---------------------------------------------------------------------------
// Global scratch (no cudaMalloc allowed)
__device__ __align__(16) __half g_xf[(size_t)(N_VOX + 1) * C_CH];
// Wt images: [axis*3+seg][n=128][k=128] fp16 (B^T, k contiguous)
__device__ __align__(16) __half g_wtf[9 * C_CH * C_CH];
__device__ __align__(16) __half g_outh[(size_t)3 * N_VOX * C_CH];  // pre-BN, fp16
__device__ float g_sum[3 * C_CH];
__device__ float g_sq [3 * C_CH];
__device__ float g_scale[3 * C_CH];
__device__ float g_shift[3 * C_CH];

// ---------------------------------------------------------------------------
__device__ __forceinline__ uint32_t smem_u32(const void* p) {
    uint32_t a;
    asm("{ .reg .u64 t; cvta.to.shared.u64 t, %1; cvt.u32.u64 %0, t; }"
        : "=r"(a) : "l"(p));
    return a;
}
__device__ __forceinline__ void cp16(uint32_t dst, const void* src) {
    asm volatile("cp.async.cg.shared.global [%0], [%1], 16;"
                 :: "r"(dst), "l"(src));
}
#define CP_COMMIT() asm volatile("cp.async.commit_group;" ::: "memory")
#define CP_WAIT1()  asm volatile("cp.async.wait_group 1;" ::: "memory")
#define CP_WAIT0()  asm volatile("cp.async.wait_group 0;" ::: "memory")

#define LDSM4(R, addr) \
    asm volatile("ldmatrix.sync.aligned.m8n8.x4.shared.b16 {%0,%1,%2,%3}, [%4];" \
        : "=r"((R)[0]), "=r"((R)[1]), "=r"((R)[2]), "=r"((R)[3]) : "r"(addr))

#define MMA16816(D, A, B0, B1) \
    asm volatile("mma.sync.aligned.m16n8k16.row.col.f32.f16.f16.f32 " \
        "{%0,%1,%2,%3}, {%4,%5,%6,%7}, {%8,%9}, {%0,%1,%2,%3};" \
        : "+f"((D)[0]), "+f"((D)[1]), "+f"((D)[2]), "+f"((D)[3]) \
        : "r"((A)[0]), "r"((A)[1]), "r"((A)[2]), "r"((A)[3]), "r"(B0), "r"(B1))

// SW128 swizzle for 128B rows: 8 x 16B chunks, chunk ^= (row & 7)
__device__ __forceinline__ uint32_t swz(int r, int c) {
    return (uint32_t)(r * 128) + (uint32_t)((c ^ (r & 7)) << 4);
}

// ---------------------------------------------------------------------------
__global__ void init_stats_kernel() {
    int t = threadIdx.x;
    if (t < 3 * C_CH) { g_sum[t] = 0.f; g_sq[t] = 0.f; }
}

// fp32 -> fp16 features (+ zero sentinel row N)
__global__ __launch_bounds__(256) void convert_kernel(const float* __restrict__ x)
{
    int i = blockIdx.x * blockDim.x + threadIdx.x;
    const int TOTP = (N_VOX + 1) * C_CH / 2;
    if (i >= TOTP) return;
    int j = i * 2;
    float2 v = (j < N_VOX * C_CH) ? *reinterpret_cast<const float2*>(x + j)
                                  : make_float2(0.f, 0.f);
    __half2 h;
    h.x = __float2half_rn(v.x);
    h.y = __float2half_rn(v.y);
    *reinterpret_cast<__half2*>(g_xf + j) = h;
}

// W[a][s][k][n] -> Wt[a*3+s][n][k] fp16
__global__ __launch_bounds__(256) void wprep_kernel(const float* __restrict__ W)
{
    int gid = blockIdx.x * blockDim.x + threadIdx.x;
    if (gid >= 9 * C_CH * C_CH) return;
    int as = gid >> 14;
    int k  = (gid >> 7) & 127;
    int n  = gid & 127;
    g_wtf[(size_t)as * C_CH * C_CH + (size_t)n * C_CH + k] = __float2half_rn(W[gid]);
}

// ---------------------------------------------------------------------------
__global__ __launch_bounds__(512, 3) void gemm_kernel(const int* __restrict__ nb)
{
    extern __shared__ char smem[];
    const uint32_t sbase = smem_u32(smem);
    const int tid  = threadIdx.x;
    const int lane = tid & 31, wid = tid >> 5;
    const int wm   = wid >> 3, wn = wid & 7;      // 2(m) x 8(n) warp grid
    const int a     = blockIdx.y;
    const int tile0 = blockIdx.x * BM;

    float* ssum = (float*)(smem + SSUM_OFF);
    float* ssq  = ssum + C_CH;
    if (tid < C_CH) { ssum[tid] = 0.f; ssq[tid] = 0.f; }

    // ---- hoisted per-thread load addresses (row r_ld = tid>>3)
    const int r_ld = tid >> 3, c_ld = tid & 7;
    const char* aBase0;
    const char* aBase1;
    const char* aBase2;
    {
        int row_g = tile0 + r_ld;
        int i0 = nb[(size_t)(a * 2) * N_VOX + row_g];
        int i2 = nb[(size_t)(a * 2 + 1) * N_VOX + row_g];
        aBase0 = (const char*)g_xf + (size_t)i0 * 256 + c_ld * 16;
        aBase1 = (const char*)g_xf + (size_t)row_g * 256 + c_ld * 16;
        aBase2 = (const char*)g_xf + (size_t)i2 * 256 + c_ld * 16;
    }
    const char* wBase = (const char*)g_wtf + (size_t)(a * 3) * 32768
                        + (size_t)r_ld * 256 + c_ld * 16;
    const uint32_t dA  = swz(r_ld, c_ld);
    const uint32_t dW1 = MAT_A + dA;
    const uint32_t dW2 = MAT_A + swz(r_ld + 64, c_ld);

    // cp.async one k64 chunk (seg = ch>>1, k-half = ch&1) into buffer ch%3
    auto load_chunk = [&](int ch) {
        const int seg = ch >> 1, kh = ch & 1;
        const char* srcA = (seg == 0) ? aBase0 : (seg == 1) ? aBase1 : aBase2;
        srcA += kh * 128;
        const char* srcW = wBase + seg * 32768 + kh * 128;
        const uint32_t bufb = sbase + (uint32_t)(ch % 3) * BUFB;
        cp16(bufb + dA,  srcA);
        cp16(bufb + dW1, srcW);
        cp16(bufb + dW2, srcW + 64 * 256);
    };

    load_chunk(0); CP_COMMIT();
    load_chunk(1); CP_COMMIT();

    float c[2][2][4];
    #pragma unroll
    for (int i = 0; i < 2; ++i)
        #pragma unroll
        for (int j = 0; j < 2; ++j)
            #pragma unroll
            for (int e = 0; e < 4; ++e) c[i][j][e] = 0.f;

    // fragment row indices / swizzle chunk phase
    int rA[2];
    rA[0] = wm * 32 + (lane & 15); rA[1] = rA[0] + 16;
    const int rB = wn * 16 + ((lane >> 4) << 3) + (lane & 7);
    const int cA = lane >> 4;
    const int cB = (lane >> 3) & 1;

    // hoisted LDSM offsets (relative to buffer base), reused by all 6 chunks
    uint32_t aOff[2][4], bOff[4];
    #pragma unroll
    for (int kk = 0; kk < 4; ++kk) {
        #pragma unroll
        for (int ma = 0; ma < 2; ++ma)
            aOff[ma][kk] = swz(rA[ma], kk * 2 + cA);
        bOff[kk] = MAT_A + swz(rB, kk * 2 + cB);
    }

    #pragma unroll
    for (int ch = 0; ch < NCHUNK; ++ch) {
        if (ch < NCHUNK - 1) CP_WAIT1(); else CP_WAIT0();
        __syncthreads();                              // data ready + prev stage free
        if (ch + 2 < NCHUNK) { load_chunk(ch + 2); CP_COMMIT(); }
        const uint32_t bufb = sbase + (uint32_t)(ch % 3) * BUFB;

        #pragma unroll
        for (int kk = 0; kk < 4; ++kk) {              // 4 x k16
            uint32_t ah[2][4], bb[4];
            LDSM4(ah[0], bufb + aOff[0][kk]);
            LDSM4(ah[1], bufb + aOff[1][kk]);
            LDSM4(bb,    bufb + bOff[kk]);

            #pragma unroll
            for (int h = 0; h < 2; ++h)
                #pragma unroll
                for (int ma = 0; ma < 2; ++ma)
                    MMA16816(c[ma][h], ah[ma], bb[h * 2], bb[h * 2 + 1]);
        }
    }

    // ---- epilogue: store pre-BN output (fp16) + per-channel stats (fp32)
    float scs[4], scq[4];
    #pragma unroll
    for (int i = 0; i < 4; ++i) { scs[i] = 0.f; scq[i] = 0.f; }

    const int rq = lane >> 2, cq2 = (lane & 3) * 2;
    #pragma unroll
    for (int ma = 0; ma < 2; ++ma) {
        #pragma unroll
        for (int na = 0; na < 2; ++na) {
            float* cc = c[ma][na];
            int r0 = tile0 + wm * 32 + ma * 16 + rq;
            int col = wn * 16 + na * 8 + cq2;
            __half* dst = g_outh + (size_t)a * N_VOX * C_CH + (size_t)r0 * C_CH + col;
            *reinterpret_cast<__half2*>(dst) =
                __floats2half2_rn(cc[0], cc[1]);
            *reinterpret_cast<__half2*>(dst + 8 * C_CH) =
                __floats2half2_rn(cc[2], cc[3]);
            scs[na * 2]     += cc[0] + cc[2];
            scs[na * 2 + 1] += cc[1] + cc[3];
            scq[na * 2]     += cc[0] * cc[0] + cc[2] * cc[2];
            scq[na * 2 + 1] += cc[1] * cc[1] + cc[3] * cc[3];
        }
    }
    #pragma unroll
    for (int na = 0; na < 2; ++na) {
        int col = wn * 16 + na * 8 + cq2;
        atomicAdd(&ssum[col],     scs[na * 2]);
        atomicAdd(&ssum[col + 1], scs[na * 2 + 1]);
        atomicAdd(&ssq[col],      scq[na * 2]);
        atomicAdd(&ssq[col + 1],  scq[na * 2 + 1]);
    }
    __syncthreads();
    if (tid < C_CH) {
        atomicAdd(&g_sum[a * C_CH + tid], ssum[tid]);
        atomicAdd(&g_sq [a * C_CH + tid], ssq[tid]);
    }
}

// ---------------------------------------------------------------------------
__global__ void finalize_kernel(const float* __restrict__ gamma,
                                const float* __restrict__ beta)
{
    int t = threadIdx.x;
    if (t >= 3 * C_CH) return;
    float invN = 1.0f / (float)N_VOX;
    float mu  = g_sum[t] * invN;
    float var = g_sq[t] * invN - mu * mu;
    float rs  = rsqrtf(var + EPSV);
    float sc  = rs * gamma[t];
    g_scale[t] = sc;
    g_shift[t] = beta[t] - mu * sc;
}

__global__ __launch_bounds__(256) void final_kernel(
    const float* __restrict__ x, float* __restrict__ out)
{
    int i4 = blockIdx.x * blockDim.x + threadIdx.x;
    const int TOT4 = N_VOX * C_CH / 4;
    if (i4 >= TOT4) return;
    int c = (i4 * 4) & (C_CH - 1);

    float4 xv = reinterpret_cast<const float4*>(x)[i4];
    float r0 = 0.f, r1 = 0.f, r2 = 0.f, r3 = 0.f;
    #pragma unroll
    for (int a = 0; a < 3; ++a) {
        const __half2* op = reinterpret_cast<const __half2*>(
            g_outh + (size_t)a * N_VOX * C_CH) + i4 * 2;
        float2 o01 = __half22float2(op[0]);
        float2 o23 = __half22float2(op[1]);
        float4 sc = *reinterpret_cast<const float4*>(&g_scale[a * C_CH + c]);
        float4 sh = *reinterpret_cast<const float4*>(&g_shift[a * C_CH + c]);
        float t0 = o01.x * sc.x + sh.x;
        float t1 = o01.y * sc.y + sh.y;
        float t2 = o23.x * sc.z + sh.z;
        float t3 = o23.y * sc.w + sh.w;
        r0 += 1.f / (1.f + __expf(-t0));
        r1 += 1.f / (1.f + __expf(-t1));
        r2 += 1.f / (1.f + __expf(-t2));
        r3 += 1.f / (1.f + __expf(-t3));
    }
    reinterpret_cast<float4*>(out)[i4] =
        make_float4(xv.x * r0, xv.y * r1, xv.z * r2, xv.w * r3);
}

// ---------------------------------------------------------------------------
extern "C" void kernel_launch(void* const* d_in, const int* in_sizes, int n_in,
                              void* d_out, int out_size)
{
    const float* x     = (const float*)d_in[0];   // [N, C]
    const int*   nb    = (const int*)  d_in[1];   // [3, 2, N]
    const float* W     = (const float*)d_in[2];   // [3, 3, C, C]
    const float* gamma = (const float*)d_in[3];   // [3, C]
    const float* beta  = (const float*)d_in[4];   // [3, C]
    float*       out   = (float*)d_out;

    cudaFuncSetAttribute(gemm_kernel,
                         cudaFuncAttributeMaxDynamicSharedMemorySize, SM_TOTAL);

    init_stats_kernel<<<1, 3 * C_CH>>>();
    {
        int totp = (N_VOX + 1) * C_CH / 2;
        convert_kernel<<<(totp + 255) / 256, 256>>>(x);
    }
    wprep_kernel<<<(9 * C_CH * C_CH + 255) / 256, 256>>>(W);
    gemm_kernel<<<dim3(NTILE, 3), 512, SM_TOTAL>>>(nb);
    finalize_kernel<<<1, 3 * C_CH>>>(gamma, beta);
    final_kernel<<<(N_VOX * C_CH / 4 + 255) / 256, 256>>>(x, out);
}

// round 10
// speedup vs baseline: 1.0302x; 1.0302x over previous
#include <cuda_runtime.h>
#include <cuda_fp16.h>
#include <cstdint>

#define N_VOX 200000
#define C_CH  128
#define NTILE2 1563                      // ceil(200000/128)
#define NUNIT (3 * NTILE2)               // 4689 (axis, tile) units
#define GRID_P 148
#define EPSV  1e-5f

#define SLOT 16384                       // one k64 A chunk / W image: 128 rows x 128B
#define SM_W     (6 * SLOT)              // A ring: slots 0..5
#define SM_STATS (12 * SLOT)             // 196608
#define SM_TOTAL (SM_STATS + 1024)       // 197632 (1 CTA/SM)

// ---------------------------------------------------------------------------
// Global scratch (no cudaMalloc allowed)
__device__ __align__(16) __half g_xf[(size_t)(N_VOX + 1) * C_CH];
// Wt images: [axis*3+seg][n=128][k=128] fp16 (B^T, k contiguous)
__device__ __align__(16) __half g_wtf[9 * C_CH * C_CH];
__device__ __align__(16) __half g_outh[(size_t)3 * N_VOX * C_CH];  // pre-BN fp16
__device__ float g_sum[3 * C_CH];
__device__ float g_sq [3 * C_CH];
__device__ float g_scale[3 * C_CH];
__device__ float g_shift[3 * C_CH];

// ---------------------------------------------------------------------------
__device__ __forceinline__ uint32_t smem_u32(const void* p) {
    uint32_t a;
    asm("{ .reg .u64 t; cvta.to.shared.u64 t, %1; cvt.u32.u64 %0, t; }"
        : "=r"(a) : "l"(p));
    return a;
}
__device__ __forceinline__ void cp16(uint32_t dst, const void* src) {
    asm volatile("cp.async.cg.shared.global [%0], [%1], 16;"
                 :: "r"(dst), "l"(src));
}
#define CP_COMMIT() asm volatile("cp.async.commit_group;" ::: "memory")
#define CP_WAIT4()  asm volatile("cp.async.wait_group 4;" ::: "memory")
#define CP_WAIT0()  asm volatile("cp.async.wait_group 0;" ::: "memory")

#define LDSM4(R, addr) \
    asm volatile("ldmatrix.sync.aligned.m8n8.x4.shared.b16 {%0,%1,%2,%3}, [%4];" \
        : "=r"((R)[0]), "=r"((R)[1]), "=r"((R)[2]), "=r"((R)[3]) : "r"(addr))

#define MMA16816(D, A, B0, B1) \
    asm volatile("mma.sync.aligned.m16n8k16.row.col.f32.f16.f16.f32 " \
        "{%0,%1,%2,%3}, {%4,%5,%6,%7}, {%8,%9}, {%0,%1,%2,%3};" \
        : "+f"((D)[0]), "+f"((D)[1]), "+f"((D)[2]), "+f"((D)[3]) \
        : "r"((A)[0]), "r"((A)[1]), "r"((A)[2]), "r"((A)[3]), "r"(B0), "r"(B1))

// SW128 swizzle for 128B rows: 8 x 16B chunks, chunk ^= (row & 7)
__device__ __forceinline__ uint32_t swz(int r, int c) {
    return (uint32_t)(r * 128) + (uint32_t)((c ^ (r & 7)) << 4);
}

// ---------------------------------------------------------------------------
__global__ void init_stats_kernel() {
    int t = threadIdx.x;
    if (t < 3 * C_CH) { g_sum[t] = 0.f; g_sq[t] = 0.f; }
}

// fp32 -> fp16 features (+ zero sentinel row N)
__global__ __launch_bounds__(256) void convert_kernel(const float* __restrict__ x)
{
    int i = blockIdx.x * blockDim.x + threadIdx.x;
    const int TOTP = (N_VOX + 1) * C_CH / 2;
    if (i >= TOTP) return;
    int j = i * 2;
    float2 v = (j < N_VOX * C_CH) ? *reinterpret_cast<const float2*>(x + j)
                                  : make_float2(0.f, 0.f);
    __half2 h;
    h.x = __float2half_rn(v.x);
    h.y = __float2half_rn(v.y);
    *reinterpret_cast<__half2*>(g_xf + j) = h;
}

// W[a][s][k][n] -> Wt[a*3+s][n][k] fp16
__global__ __launch_bounds__(256) void wprep_kernel(const float* __restrict__ W)
{
    int gid = blockIdx.x * blockDim.x + threadIdx.x;
    if (gid >= 9 * C_CH * C_CH) return;
    int as = gid >> 14;
    int k  = (gid >> 7) & 127;
    int n  = gid & 127;
    g_wtf[(size_t)as * C_CH * C_CH + (size_t)n * C_CH + k] = __float2half_rn(W[gid]);
}

// ---------------------------------------------------------------------------
// Persistent gemm: 148 CTAs x 1024 threads; W resident; 6-deep A ring.
__global__ __launch_bounds__(1024, 1) void gemm_kernel(const int* __restrict__ nb)
{
    extern __shared__ char smem[];
    const uint32_t sbase = smem_u32(smem);
    const int tid  = threadIdx.x;
    const int lane = tid & 31, wid = tid >> 5;
    const int wm   = wid >> 3, wn = wid & 7;        // 4(m) x 8(n) warps

    float* ssum = (float*)(smem + SM_STATS);
    float* ssq  = ssum + C_CH;
    if (tid < 2 * C_CH) ssum[tid] = 0.f;            // zero both arrays

    const int r_ld = tid >> 3, c_ld = tid & 7;      // A/W loader mapping
    const uint32_t dA = swz(r_ld, c_ld);

    int u = blockIdx.x;                             // first units are axis 0
    int aCur = 0, tCur = u;

    // ---- W loader: 6 images of 16KB into SM_W (6 cp16 / thread)
    auto loadW = [&](int a) {
        #pragma unroll
        for (int it = 0; it < 6; ++it) {
            int slot = tid + it * 1024;
            int img = slot >> 10, row = (slot >> 3) & 127, cc = slot & 7;
            const char* src = (const char*)g_wtf
                + (size_t)(a * 3 + (img >> 1)) * 32768
                + row * 256 + (img & 1) * 128 + cc * 16;
            cp16(sbase + SM_W + (uint32_t)img * SLOT + swz(row, cc), src);
        }
    };
    // ---- gather-index loader for unit uu (per-thread row r_ld)
    auto loadIdx = [&](int uu, int* idx) {
        int aa = (uu >= 2 * NTILE2) ? 2 : (uu >= NTILE2 ? 1 : 0);
        int tt = uu - aa * NTILE2;
        int row_g = tt * 128 + r_ld;
        if (row_g >= N_VOX) { idx[0] = N_VOX; idx[1] = N_VOX; idx[2] = N_VOX; }
        else {
            idx[0] = nb[(size_t)(aa * 2) * N_VOX + row_g];
            idx[1] = row_g;
            idx[2] = nb[(size_t)(aa * 2 + 1) * N_VOX + row_g];
        }
    };
    int curI[3], nxtI[3];
    loadIdx(u, curI);
    { int un = u + GRID_P; loadIdx(un < NUNIT ? un : u, nxtI); }

    loadW(0); CP_COMMIT(); CP_WAIT0(); __syncthreads();

    // ---- A chunk prefetch: chunk j of a unit always lands in ring slot j
    auto pfA = [&](const int* idx, int j) {
        const int seg = j >> 1, kh = j & 1;
        const char* src = (const char*)g_xf
            + (size_t)idx[seg] * 256 + kh * 128 + c_ld * 16;
        cp16(sbase + (uint32_t)j * SLOT + dA, src);
        CP_COMMIT();
    };
    #pragma unroll
    for (int j = 0; j < 5; ++j) pfA(curI, j);       // prime chunks 0..4

    // ---- fragment offsets (ring-slot relative; W shares the j*SLOT shift)
    const int rA0 = wm * 32 + (lane & 15);
    const int rB  = wn * 16 + ((lane >> 4) << 3) + (lane & 7);
    const int cA  = lane >> 4, cB = (lane >> 3) & 1;
    uint32_t aOff[2][4], bOff[4];
    #pragma unroll
    for (int kk = 0; kk < 4; ++kk) {
        aOff[0][kk] = swz(rA0,      kk * 2 + cA);
        aOff[1][kk] = swz(rA0 + 16, kk * 2 + cA);
        bOff[kk]    = SM_W + swz(rB, kk * 2 + cB);
    }

    float c[2][2][4];
    #pragma unroll
    for (int i = 0; i < 2; ++i)
        #pragma unroll
        for (int j = 0; j < 2; ++j)
            #pragma unroll
            for (int e = 0; e < 4; ++e) c[i][j][e] = 0.f;

    const int rq = lane >> 2, cq2 = (lane & 3) * 2;

    while (true) {
        const int tile0 = tCur * 128;

        #pragma unroll 1
        for (int j = 0; j < 6; ++j) {
            CP_WAIT4();                              // chunk j arrived
            __syncthreads();                         // + slot j-1 fully consumed
            if (j == 0) pfA(curI, 5); else pfA(nxtI, j - 1);
            const uint32_t base = sbase + (uint32_t)j * SLOT;

            #pragma unroll
            for (int kk = 0; kk < 4; ++kk) {
                uint32_t ah0[4], ah1[4], bb[4];
                LDSM4(ah0, base + aOff[0][kk]);
                LDSM4(ah1, base + aOff[1][kk]);
                LDSM4(bb,  base + bOff[kk]);         // W image j
                MMA16816(c[0][0], ah0, bb[0], bb[1]);
                MMA16816(c[1][0], ah1, bb[0], bb[1]);
                MMA16816(c[0][1], ah0, bb[2], bb[3]);
                MMA16816(c[1][1], ah1, bb[2], bb[3]);
            }
        }

        // ---- epilogue: fp16 store + stats (pad rows are exact zeros -> no bias)
        float scs[4] = {0, 0, 0, 0}, scq[4] = {0, 0, 0, 0};
        #pragma unroll
        for (int ma = 0; ma < 2; ++ma) {
            #pragma unroll
            for (int na = 0; na < 2; ++na) {
                float* cc = c[ma][na];
                int r0 = tile0 + wm * 32 + ma * 16 + rq;
                int col = wn * 16 + na * 8 + cq2;
                __half* dst = g_outh + (size_t)aCur * N_VOX * C_CH
                              + (size_t)r0 * C_CH + col;
                if (r0 < N_VOX)
                    *reinterpret_cast<__half2*>(dst) = __floats2half2_rn(cc[0], cc[1]);
                if (r0 + 8 < N_VOX)
                    *reinterpret_cast<__half2*>(dst + 8 * C_CH) =
                        __floats2half2_rn(cc[2], cc[3]);
                scs[na * 2]     += cc[0] + cc[2];
                scs[na * 2 + 1] += cc[1] + cc[3];
                scq[na * 2]     += cc[0] * cc[0] + cc[2] * cc[2];
                scq[na * 2 + 1] += cc[1] * cc[1] + cc[3] * cc[3];
            }
        }
        #pragma unroll
        for (int na = 0; na < 2; ++na) {
            int col = wn * 16 + na * 8 + cq2;
            atomicAdd(&ssum[col],     scs[na * 2]);
            atomicAdd(&ssum[col + 1], scs[na * 2 + 1]);
            atomicAdd(&ssq[col],      scq[na * 2]);
            atomicAdd(&ssq[col + 1],  scq[na * 2 + 1]);
        }
        __syncthreads();
        if (tid < C_CH) {
            atomicAdd(&g_sum[aCur * C_CH + tid], ssum[tid]);
            atomicAdd(&g_sq [aCur * C_CH + tid], ssq[tid]);
            ssum[tid] = 0.f; ssq[tid] = 0.f;
        }
        #pragma unroll
        for (int i = 0; i < 2; ++i)
            #pragma unroll
            for (int j = 0; j < 2; ++j)
                #pragma unroll
                for (int e = 0; e < 4; ++e) c[i][j][e] = 0.f;

        // ---- advance to next unit
        u += GRID_P;
        if (u >= NUNIT) break;
        int aN = (u >= 2 * NTILE2) ? 2 : (u >= NTILE2 ? 1 : 0);
        tCur = u - aN * NTILE2;
        curI[0] = nxtI[0]; curI[1] = nxtI[1]; curI[2] = nxtI[2];
        { int un = u + GRID_P; if (un < NUNIT) loadIdx(un, nxtI); }
        if (aN != aCur) {                            // rare: <=2 times per CTA
            aCur = aN;
            CP_WAIT0(); __syncthreads();             // drain (prefetched A stays valid)
            loadW(aCur); CP_COMMIT(); CP_WAIT0(); __syncthreads();
        }
    }
    CP_WAIT0();                                      // retire in-flight prefetches
}

// ---------------------------------------------------------------------------
__global__ void finalize_kernel(const float* __restrict__ gamma,
                                const float* __restrict__ beta)
{
    int t = threadIdx.x;
    if (t >= 3 * C_CH) return;
    float invN = 1.0f / (float)N_VOX;
    float mu  = g_sum[t] * invN;
    float var = g_sq[t] * invN - mu * mu;
    float rs  = rsqrtf(var + EPSV);
    float sc  = rs * gamma[t];
    g_scale[t] = sc;
    g_shift[t] = beta[t] - mu * sc;
}

__global__ __launch_bounds__(256) void final_kernel(
    const float* __restrict__ x, float* __restrict__ out)
{
    int i4 = blockIdx.x * blockDim.x + threadIdx.x;
    const int TOT4 = N_VOX * C_CH / 4;
    if (i4 >= TOT4) return;
    int c = (i4 * 4) & (C_CH - 1);

    float4 xv = reinterpret_cast<const float4*>(x)[i4];
    float r0 = 0.f, r1 = 0.f, r2 = 0.f, r3 = 0.f;
    #pragma unroll
    for (int a = 0; a < 3; ++a) {
        const __half2* op = reinterpret_cast<const __half2*>(
            g_outh + (size_t)a * N_VOX * C_CH) + i4 * 2;
        float2 o01 = __half22float2(op[0]);
        float2 o23 = __half22float2(op[1]);
        float4 sc = *reinterpret_cast<const float4*>(&g_scale[a * C_CH + c]);
        float4 sh = *reinterpret_cast<const float4*>(&g_shift[a * C_CH + c]);
        float t0 = o01.x * sc.x + sh.x;
        float t1 = o01.y * sc.y + sh.y;
        float t2 = o23.x * sc.z + sh.z;
        float t3 = o23.y * sc.w + sh.w;
        r0 += 1.f / (1.f + __expf(-t0));
        r1 += 1.f / (1.f + __expf(-t1));
        r2 += 1.f / (1.f + __expf(-t2));
        r3 += 1.f / (1.f + __expf(-t3));
    }
    reinterpret_cast<float4*>(out)[i4] =
        make_float4(xv.x * r0, xv.y * r1, xv.z * r2, xv.w * r3);
}

// ---------------------------------------------------------------------------
extern "C" void kernel_launch(void* const* d_in, const int* in_sizes, int n_in,
                              void* d_out, int out_size)
{
    const float* x     = (const float*)d_in[0];   // [N, C]
    const int*   nb    = (const int*)  d_in[1];   // [3, 2, N]
    const float* W     = (const float*)d_in[2];   // [3, 3, C, C]
    const float* gamma = (const float*)d_in[3];   // [3, C]
    const float* beta  = (const float*)d_in[4];   // [3, C]
    float*       out   = (float*)d_out;

    cudaFuncSetAttribute(gemm_kernel,
                         cudaFuncAttributeMaxDynamicSharedMemorySize, SM_TOTAL);

    init_stats_kernel<<<1, 3 * C_CH>>>();
    {
        int totp = (N_VOX + 1) * C_CH / 2;
        convert_kernel<<<(totp + 255) / 256, 256>>>(x);
    }
    wprep_kernel<<<(9 * C_CH * C_CH + 255) / 256, 256>>>(W);
    gemm_kernel<<<GRID_P, 1024, SM_TOTAL>>>(nb);
    finalize_kernel<<<1, 3 * C_CH>>>(gamma, beta);
    final_kernel<<<(N_VOX * C_CH / 4 + 255) / 256, 256>>>(x, out);
}

// round 13
// speedup vs baseline: 1.1627x; 1.1286x over previous
#include <cuda_runtime.h>
#include <cuda_fp16.h>
#include <cstdint>

#define N_VOX 200000
#define C_CH  128
#define BM    64
#define NTILE (N_VOX / BM)               // 3125 exact
#define EPSV  1e-5f

#define NCHUNK 6                         // 384 / 64
#define MAT_A  8192                      // 64 rows * 128B
#define MAT_W  16384                     // 128 rows * 128B
#define BUFB   (MAT_A + MAT_W)           // 24576
#define SSUM_OFF (3 * BUFB)              // 73728
#define SM_TOTAL (SSUM_OFF + 1024)       // 74752 -> 3 CTAs/SM

// ---------------------------------------------------------------------------
// Global scratch (no cudaMalloc allowed)
__device__ __align__(16) __half g_xf[(size_t)(N_VOX + 1) * C_CH];
// Wt images: [axis*3+seg][n=128][k=128] fp16 (B^T, k contiguous)
__device__ __align__(16) __half g_wtf[9 * C_CH * C_CH];
__device__ __align__(16) __half g_outh[(size_t)3 * N_VOX * C_CH];  // pre-BN fp16
__device__ float g_sum[3 * C_CH];
__device__ float g_sq [3 * C_CH];
__device__ float g_scale[3 * C_CH];
__device__ float g_shift[3 * C_CH];

// ---------------------------------------------------------------------------
__device__ __forceinline__ uint32_t smem_u32(const void* p) {
    uint32_t a;
    asm("{ .reg .u64 t; cvta.to.shared.u64 t, %1; cvt.u32.u64 %0, t; }"
        : "=r"(a) : "l"(p));
    return a;
}
__device__ __forceinline__ void cp16(uint32_t dst, const void* src) {
    asm volatile("cp.async.cg.shared.global [%0], [%1], 16;"
                 :: "r"(dst), "l"(src));
}
#define CP_COMMIT() asm volatile("cp.async.commit_group;" ::: "memory")
#define CP_WAIT1()  asm volatile("cp.async.wait_group 1;" ::: "memory")
#define CP_WAIT0()  asm volatile("cp.async.wait_group 0;" ::: "memory")

#define LDSM4(R, addr) \
    asm volatile("ldmatrix.sync.aligned.m8n8.x4.shared.b16 {%0,%1,%2,%3}, [%4];" \
        : "=r"((R)[0]), "=r"((R)[1]), "=r"((R)[2]), "=r"((R)[3]) : "r"(addr))

#define MMA16816(D, A, B0, B1) \
    asm volatile("mma.sync.aligned.m16n8k16.row.col.f32.f16.f16.f32 " \
        "{%0,%1,%2,%3}, {%4,%5,%6,%7}, {%8,%9}, {%0,%1,%2,%3};" \
        : "+f"((D)[0]), "+f"((D)[1]), "+f"((D)[2]), "+f"((D)[3]) \
        : "r"((A)[0]), "r"((A)[1]), "r"((A)[2]), "r"((A)[3]), "r"(B0), "r"(B1))

// SW128 swizzle for 128B rows: 8 x 16B chunks, chunk ^= (row & 7)
__device__ __forceinline__ uint32_t swz(int r, int c) {
    return (uint32_t)(r * 128) + (uint32_t)((c ^ (r & 7)) << 4);
}

// ---------------------------------------------------------------------------
__global__ void init_stats_kernel() {
    int t = threadIdx.x;
    if (t < 3 * C_CH) { g_sum[t] = 0.f; g_sq[t] = 0.f; }
}

// fp32 -> fp16 features (+ zero sentinel row N)
__global__ __launch_bounds__(256) void convert_kernel(const float* __restrict__ x)
{
    int i = blockIdx.x * blockDim.x + threadIdx.x;
    const int TOTP = (N_VOX + 1) * C_CH / 2;
    if (i >= TOTP) return;
    int j = i * 2;
    float2 v = (j < N_VOX * C_CH) ? *reinterpret_cast<const float2*>(x + j)
                                  : make_float2(0.f, 0.f);
    __half2 h;
    h.x = __float2half_rn(v.x);
    h.y = __float2half_rn(v.y);
    *reinterpret_cast<__half2*>(g_xf + j) = h;
}

// W[a][s][k][n] -> Wt[a*3+s][n][k] fp16
__global__ __launch_bounds__(256) void wprep_kernel(const float* __restrict__ W)
{
    int gid = blockIdx.x * blockDim.x + threadIdx.x;
    if (gid >= 9 * C_CH * C_CH) return;
    int as = gid >> 14;
    int k  = (gid >> 7) & 127;
    int n  = gid & 127;
    g_wtf[(size_t)as * C_CH * C_CH + (size_t)n * C_CH + k] = __float2half_rn(W[gid]);
}

// ---------------------------------------------------------------------------
__global__ __launch_bounds__(512, 3) void gemm_kernel(const int* __restrict__ nb)
{
    extern __shared__ char smem[];
    const uint32_t sbase = smem_u32(smem);
    const int tid  = threadIdx.x;
    const int lane = tid & 31, wid = tid >> 5;
    const int wm   = wid >> 3, wn = wid & 7;      // 2(m) x 8(n) warp grid
    const int a     = blockIdx.y;
    const int tile0 = blockIdx.x * BM;

    float* ssum = (float*)(smem + SSUM_OFF);
    float* ssq  = ssum + C_CH;
    if (tid < C_CH) { ssum[tid] = 0.f; ssq[tid] = 0.f; }

    // per-thread gather indices for A row r_ld = tid>>3
    const int r_ld = tid >> 3, c_ld = tid & 7;
    int iSeg[3];
    {
        int row_g = tile0 + r_ld;
        iSeg[0] = nb[(size_t)(a * 2) * N_VOX + row_g];
        iSeg[1] = row_g;
        iSeg[2] = nb[(size_t)(a * 2 + 1) * N_VOX + row_g];
    }
    const char* wbaseA = (const char*)g_wtf + (size_t)(a * 3) * 32768;

    // cp.async one k64 chunk (seg = ch>>1, k-half = ch&1) into buffer ch%3
    auto load_chunk = [&](int ch) {
        const int seg = ch >> 1, kh = ch & 1;
        const char* srcA = (const char*)g_xf + (size_t)iSeg[seg] * 256 + kh * 128;
        const char* wseg = wbaseA + (size_t)seg * 32768 + kh * 128;
        const uint32_t bufb = sbase + (uint32_t)(ch % 3) * BUFB;
        cp16(bufb + swz(r_ld, c_ld), srcA + c_ld * 16);
        cp16(bufb + MAT_A + swz(r_ld, c_ld),
             wseg + (size_t)r_ld * 256 + c_ld * 16);
        cp16(bufb + MAT_A + swz(r_ld + 64, c_ld),
             wseg + (size_t)(r_ld + 64) * 256 + c_ld * 16);
    };

    load_chunk(0); CP_COMMIT();
    load_chunk(1); CP_COMMIT();

    float c[2][2][4];
    #pragma unroll
    for (int i = 0; i < 2; ++i)
        #pragma unroll
        for (int j = 0; j < 2; ++j)
            #pragma unroll
            for (int e = 0; e < 4; ++e) c[i][j][e] = 0.f;

    // fragment row indices / swizzle chunk phase
    int rA[2];
    rA[0] = wm * 32 + (lane & 15); rA[1] = rA[0] + 16;
    const int rB = wn * 16 + ((lane >> 4) << 3) + (lane & 7);
    const int cA = lane >> 4;
    const int cB = (lane >> 3) & 1;

    #pragma unroll 1
    for (int ch = 0; ch < NCHUNK; ++ch) {
        if (ch < NCHUNK - 1) CP_WAIT1(); else CP_WAIT0();
        __syncthreads();                              // data ready + prev stage free
        if (ch + 2 < NCHUNK) { load_chunk(ch + 2); CP_COMMIT(); }
        const uint32_t bufb = sbase + (uint32_t)(ch % 3) * BUFB;

        #pragma unroll
        for (int kk = 0; kk < 4; ++kk) {              // 4 x k16
            uint32_t ah[2][4], bb[4];
            #pragma unroll
            for (int ma = 0; ma < 2; ++ma)
                LDSM4(ah[ma], bufb + swz(rA[ma], kk * 2 + cA));
            LDSM4(bb, bufb + MAT_A + swz(rB, kk * 2 + cB));

            #pragma unroll
            for (int h = 0; h < 2; ++h)
                #pragma unroll
                for (int ma = 0; ma < 2; ++ma)
                    MMA16816(c[ma][h], ah[ma], bb[h * 2], bb[h * 2 + 1]);
        }
    }

    // ---- epilogue: fp16 store + per-channel stats (fp32 accumulators)
    float scs[4], scq[4];
    #pragma unroll
    for (int i = 0; i < 4; ++i) { scs[i] = 0.f; scq[i] = 0.f; }

    const int rq = lane >> 2, cq2 = (lane & 3) * 2;
    #pragma unroll
    for (int ma = 0; ma < 2; ++ma) {
        #pragma unroll
        for (int na = 0; na < 2; ++na) {
            float* cc = c[ma][na];
            int r0 = tile0 + wm * 32 + ma * 16 + rq;
            int col = wn * 16 + na * 8 + cq2;
            __half* dst = g_outh + (size_t)a * N_VOX * C_CH + (size_t)r0 * C_CH + col;
            *reinterpret_cast<__half2*>(dst) = __floats2half2_rn(cc[0], cc[1]);
            *reinterpret_cast<__half2*>(dst + 8 * C_CH) = __floats2half2_rn(cc[2], cc[3]);
            scs[na * 2]     += cc[0] + cc[2];
            scs[na * 2 + 1] += cc[1] + cc[3];
            scq[na * 2]     += cc[0] * cc[0] + cc[2] * cc[2];
            scq[na * 2 + 1] += cc[1] * cc[1] + cc[3] * cc[3];
        }
    }
    #pragma unroll
    for (int na = 0; na < 2; ++na) {
        int col = wn * 16 + na * 8 + cq2;
        atomicAdd(&ssum[col],     scs[na * 2]);
        atomicAdd(&ssum[col + 1], scs[na * 2 + 1]);
        atomicAdd(&ssq[col],      scq[na * 2]);
        atomicAdd(&ssq[col + 1],  scq[na * 2 + 1]);
    }
    __syncthreads();
    if (tid < C_CH) {
        atomicAdd(&g_sum[a * C_CH + tid], ssum[tid]);
        atomicAdd(&g_sq [a * C_CH + tid], ssq[tid]);
    }
}

// ---------------------------------------------------------------------------
__global__ void finalize_kernel(const float* __restrict__ gamma,
                                const float* __restrict__ beta)
{
    int t = threadIdx.x;
    if (t >= 3 * C_CH) return;
    float invN = 1.0f / (float)N_VOX;
    float mu  = g_sum[t] * invN;
    float var = g_sq[t] * invN - mu * mu;
    float rs  = rsqrtf(var + EPSV);
    float sc  = rs * gamma[t];
    g_scale[t] = sc;
    g_shift[t] = beta[t] - mu * sc;
}

__global__ __launch_bounds__(256) void final_kernel(
    const float* __restrict__ x, float* __restrict__ out)
{
    int i4 = blockIdx.x * blockDim.x + threadIdx.x;
    const int TOT4 = N_VOX * C_CH / 4;
    if (i4 >= TOT4) return;
    int c = (i4 * 4) & (C_CH - 1);

    float4 xv = reinterpret_cast<const float4*>(x)[i4];
    float r0 = 0.f, r1 = 0.f, r2 = 0.f, r3 = 0.f;
    #pragma unroll
    for (int a = 0; a < 3; ++a) {
        const __half2* op = reinterpret_cast<const __half2*>(
            g_outh + (size_t)a * N_VOX * C_CH) + i4 * 2;
        float2 o01 = __half22float2(op[0]);
        float2 o23 = __half22float2(op[1]);
        float4 sc = *reinterpret_cast<const float4*>(&g_scale[a * C_CH + c]);
        float4 sh = *reinterpret_cast<const float4*>(&g_shift[a * C_CH + c]);
        float t0 = o01.x * sc.x + sh.x;
        float t1 = o01.y * sc.y + sh.y;
        float t2 = o23.x * sc.z + sh.z;
        float t3 = o23.y * sc.w + sh.w;
        r0 += 1.f / (1.f + __expf(-t0));
        r1 += 1.f / (1.f + __expf(-t1));
        r2 += 1.f / (1.f + __expf(-t2));
        r3 += 1.f / (1.f + __expf(-t3));
    }
    reinterpret_cast<float4*>(out)[i4] =
        make_float4(xv.x * r0, xv.y * r1, xv.z * r2, xv.w * r3);
}

// ---------------------------------------------------------------------------
extern "C" void kernel_launch(void* const* d_in, const int* in_sizes, int n_in,
                              void* d_out, int out_size)
{
    const float* x     = (const float*)d_in[0];   // [N, C]
    const int*   nb    = (const int*)  d_in[1];   // [3, 2, N]
    const float* W     = (const float*)d_in[2];   // [3, 3, C, C]
    const float* gamma = (const float*)d_in[3];   // [3, C]
    const float* beta  = (const float*)d_in[4];   // [3, C]
    float*       out   = (float*)d_out;

    cudaFuncSetAttribute(gemm_kernel,
                         cudaFuncAttributeMaxDynamicSharedMemorySize, SM_TOTAL);

    init_stats_kernel<<<1, 3 * C_CH>>>();
    {
        int totp = (N_VOX + 1) * C_CH / 2;
        convert_kernel<<<(totp + 255) / 256, 256>>>(x);
    }
    wprep_kernel<<<(9 * C_CH * C_CH + 255) / 256, 256>>>(W);
    gemm_kernel<<<dim3(NTILE, 3), 512, SM_TOTAL>>>(nb);
    finalize_kernel<<<1, 3 * C_CH>>>(gamma, beta);
    final_kernel<<<(N_VOX * C_CH / 4 + 255) / 256, 256>>>(x, out);
}